// round 4
// baseline (speedup 1.0000x reference)
#include <cuda_runtime.h>
#include <cuda_bf16.h>
#include <cstdint>
#include <cstddef>

#define BATCH   2
#define NTOK    2048
#define DMODEL  1024
#define HEADS   16
#define HD      64
#define MROWS   (BATCH*NTOK)  // 4096
#define WSZ     ((size_t)DMODEL * DMODEL)

// ======================= helpers ============================================
__device__ __forceinline__ uint32_t smem_u32(const void* p) {
    uint32_t a;
    asm("{ .reg .u64 t; cvta.to.shared.u64 t, %1; cvt.u32.u64 %0, t; }" : "=r"(a) : "l"(p));
    return a;
}
__device__ __forceinline__ void ldsm_x4(uint32_t r[4], uint32_t a) {
    asm volatile("ldmatrix.sync.aligned.m8n8.x4.shared.b16 {%0,%1,%2,%3}, [%4];"
        : "=r"(r[0]), "=r"(r[1]), "=r"(r[2]), "=r"(r[3]) : "r"(a));
}
__device__ __forceinline__ void ldsm_x4t(uint32_t r[4], uint32_t a) {
    asm volatile("ldmatrix.sync.aligned.m8n8.x4.trans.shared.b16 {%0,%1,%2,%3}, [%4];"
        : "=r"(r[0]), "=r"(r[1]), "=r"(r[2]), "=r"(r[3]) : "r"(a));
}
__device__ __forceinline__ void mma_bf16(float* c, const uint32_t* a, uint32_t b0, uint32_t b1) {
    asm volatile("mma.sync.aligned.m16n8k16.row.col.f32.bf16.bf16.f32 "
        "{%0,%1,%2,%3}, {%4,%5,%6,%7}, {%8,%9}, {%0,%1,%2,%3};"
        : "+f"(c[0]), "+f"(c[1]), "+f"(c[2]), "+f"(c[3])
        : "r"(a[0]), "r"(a[1]), "r"(a[2]), "r"(a[3]), "r"(b0), "r"(b1));
}
__device__ __forceinline__ void cp16(uint32_t sa, const void* g) {
    asm volatile("cp.async.cg.shared.global [%0], [%1], 16;"
        :: "r"(sa), "l"(__cvta_generic_to_global(g)) : "memory");
}
#define CP_COMMIT() asm volatile("cp.async.commit_group;" ::: "memory")
#define CP_WAIT0()  asm volatile("cp.async.wait_group 0;"  ::: "memory")

__device__ __forceinline__ ushort bfhi(float x) {
    return __bfloat16_as_ushort(__float2bfloat16(x));
}
__device__ __forceinline__ void split2(float a, float b, uint32_t& hi, uint32_t& lo) {
    ushort ah = bfhi(a), bh = bfhi(b);
    float ar = a - __bfloat162float(__ushort_as_bfloat16(ah));
    float br = b - __bfloat162float(__ushort_as_bfloat16(bh));
    hi = (uint32_t)ah | ((uint32_t)bh << 16);
    lo = (uint32_t)bfhi(ar) | ((uint32_t)bfhi(br) << 16);
}

// ======================= scratch (device globals) ===========================
__device__ __align__(16) __nv_bfloat16 g_hpe_hi[MROWS * DMODEL];
__device__ __align__(16) __nv_bfloat16 g_hpe_lo[MROWS * DMODEL];
__device__ __align__(16) __nv_bfloat16 g_w_hi[4 * DMODEL * DMODEL];
__device__ __align__(16) __nv_bfloat16 g_w_lo[4 * DMODEL * DMODEL];
__device__ __align__(16) __nv_bfloat16 g_qkv_hi[3 * MROWS * DMODEL];
__device__ __align__(16) __nv_bfloat16 g_qkv_lo[3 * MROWS * DMODEL];
__device__ __align__(16) __nv_bfloat16 g_ctx_hi[MROWS * DMODEL];
__device__ __align__(16) __nv_bfloat16 g_ctx_lo[MROWS * DMODEL];
__device__ __align__(16) float g_pb[BATCH * NTOK];
__device__ __align__(16) float g_bias3[3 * DMODEL];

// ======================= prep kernels =======================================
__global__ void build_hpe_split_kernel(const float* __restrict__ h,
                                       __nv_bfloat16* __restrict__ hi,
                                       __nv_bfloat16* __restrict__ lo) {
    int idx = blockIdx.x * blockDim.x + threadIdx.x;
    int row = idx >> 8;
    int d   = (idx & 255) * 4;
    int n   = row & (NTOK - 1);
    const float c1 = -9.210340371976184f / 1024.0f;
    float fn = (float)n;
    float div0 = expf((float)d * c1);
    float div1 = expf((float)(d + 2) * c1);
    float s0, c0, s1, c1v;
    sincosf(fn * div0, &s0, &c0);
    sincosf(fn * div1, &s1, &c1v);
    float4 v = reinterpret_cast<const float4*>(h)[idx];
    float x0 = v.x + s0, x1 = v.y + c0, x2 = v.z + s1, x3 = v.w + c1v;
    uint32_t h01, l01, h23, l23;
    split2(x0, x1, h01, l01);
    split2(x2, x3, h23, l23);
    reinterpret_cast<uint2*>(hi)[idx] = make_uint2(h01, h23);
    reinterpret_cast<uint2*>(lo)[idx] = make_uint2(l01, l23);
}

__global__ void split_weights_kernel(const float* __restrict__ Wq, const float* __restrict__ Wk,
                                     const float* __restrict__ Wv, const float* __restrict__ Wo,
                                     __nv_bfloat16* __restrict__ hi, __nv_bfloat16* __restrict__ lo) {
    int m = blockIdx.y;
    const float* src = (m == 0) ? Wq : (m == 1) ? Wk : (m == 2) ? Wv : Wo;
    int idx = blockIdx.x * blockDim.x + threadIdx.x;
    float4 v = reinterpret_cast<const float4*>(src)[idx];
    uint32_t h01, l01, h23, l23;
    split2(v.x, v.y, h01, l01);
    split2(v.z, v.w, h23, l23);
    size_t base = (size_t)m * (DMODEL * DMODEL / 4);
    reinterpret_cast<uint2*>(hi)[base + idx] = make_uint2(h01, h23);
    reinterpret_cast<uint2*>(lo)[base + idx] = make_uint2(l01, l23);
}

__global__ void build_pbias_kernel(const float* __restrict__ probs,
                                   const float* __restrict__ scale,
                                   float* __restrict__ pb) {
    int i = blockIdx.x * blockDim.x + threadIdx.x;
    if (i < BATCH * NTOK)
        pb[i] = scale[0] * logf(probs[i] + 1e-8f);
}

__global__ void pack_bias_kernel(const float* __restrict__ bq, const float* __restrict__ bk,
                                 const float* __restrict__ bv, float* __restrict__ b3) {
    int i = blockIdx.x * blockDim.x + threadIdx.x;
    if (i < DMODEL)           b3[i] = bq[i];
    else if (i < 2 * DMODEL)  b3[i] = bk[i - DMODEL];
    else if (i < 3 * DMODEL)  b3[i] = bv[i - 2 * DMODEL];
}

// ================= HMMA split-bf16 GEMM (cp.async double-buffered) ==========
// C[4096, Ntot] = A @ W^T + bias. Tile 128x128, K-chunk 64, 256 thr (8 warps).
// B/bias/C stacked over matrices (1024 cols each). smem pitch 144B.
#define GPB 144
#define G_STAGE 73728          // 4 bufs x 128 x 144
#define GEMM_SMEM (2 * G_STAGE)  // 147456

template<bool F32OUT>
__global__ __launch_bounds__(256)
void gemm_cp_kernel(const __nv_bfloat16* __restrict__ Ahi, const __nv_bfloat16* __restrict__ Alo,
                    const __nv_bfloat16* __restrict__ Bhi, const __nv_bfloat16* __restrict__ Blo,
                    const float* __restrict__ bias,
                    float* __restrict__ Cf,
                    __nv_bfloat16* __restrict__ Chi, __nv_bfloat16* __restrict__ Clo) {
    extern __shared__ __align__(16) char sm[];
    const uint32_t sb = smem_u32(sm);

    const int tid = threadIdx.x, lane = tid & 31, wid = tid >> 5;
    const int wm = wid & 3, wn = wid >> 2;
    const int m0 = blockIdx.y * 128;
    const int ng = blockIdx.x * 128;
    const int mat = ng >> 10;
    const int n0 = ng & 1023;

    const __nv_bfloat16* Bh = Bhi + (size_t)mat * WSZ;
    const __nv_bfloat16* Bl = Blo + (size_t)mat * WSZ;

    auto load_stage = [&](int stage, int kc) {
        uint32_t st = sb + stage * G_STAGE;
#pragma unroll
        for (int t = 0; t < 4; t++) {
            int u = tid + t * 256;
            int r = u >> 3, s = u & 7;
            uint32_t d = (uint32_t)(r * GPB + s * 16);
            size_t ga = (size_t)(m0 + r) * DMODEL + kc * 64 + s * 8;
            cp16(st + d,          Ahi + ga);
            cp16(st + 18432 + d,  Alo + ga);
            size_t gb = (size_t)(n0 + r) * DMODEL + kc * 64 + s * 8;
            cp16(st + 36864 + d,  Bh + gb);
            cp16(st + 55296 + d,  Bl + gb);
        }
    };

    float acc[2][8][4];
#pragma unroll
    for (int mi = 0; mi < 2; mi++)
#pragma unroll
        for (int nj = 0; nj < 8; nj++)
#pragma unroll
            for (int q = 0; q < 4; q++) acc[mi][nj][q] = 0.0f;

    const int lr = (lane & 7) + ((lane >> 3) & 1) * 8;
    const int lk = (lane >> 4) * 8;

    load_stage(0, 0);
    CP_COMMIT();

    for (int kc = 0; kc < 16; kc++) {
        const int cur = kc & 1;
        CP_WAIT0();
        __syncthreads();
        if (kc + 1 < 16) {
            load_stage(cur ^ 1, kc + 1);
            CP_COMMIT();
        }
        const uint32_t st = sb + cur * G_STAGE;
#pragma unroll
        for (int ks = 0; ks < 4; ks++) {
            uint32_t ah[2][4], al[2][4];
#pragma unroll
            for (int mi = 0; mi < 2; mi++) {
                uint32_t off = (uint32_t)(wm * 32 + mi * 16 + lr) * GPB + (ks * 16 + lk) * 2;
                ldsm_x4(ah[mi], st + off);
                ldsm_x4(al[mi], st + 18432u + off);
            }
#pragma unroll
            for (int np = 0; np < 4; np++) {
                uint32_t off = (uint32_t)(wn * 64 + np * 16 + lr) * GPB + (ks * 16 + lk) * 2;
                uint32_t bh[4], bl[4];
                ldsm_x4(bh, st + 36864u + off);
                ldsm_x4(bl, st + 55296u + off);
#pragma unroll
                for (int mi = 0; mi < 2; mi++) {
                    mma_bf16(acc[mi][2 * np],     ah[mi], bh[0], bh[2]);
                    mma_bf16(acc[mi][2 * np + 1], ah[mi], bh[1], bh[3]);
                    mma_bf16(acc[mi][2 * np],     ah[mi], bl[0], bl[2]);
                    mma_bf16(acc[mi][2 * np + 1], ah[mi], bl[1], bl[3]);
                    mma_bf16(acc[mi][2 * np],     al[mi], bh[0], bh[2]);
                    mma_bf16(acc[mi][2 * np + 1], al[mi], bh[1], bh[3]);
                }
            }
        }
    }

    // epilogue
#pragma unroll
    for (int mi = 0; mi < 2; mi++) {
        int row = m0 + wm * 32 + mi * 16 + (lane >> 2);
#pragma unroll
        for (int nj = 0; nj < 8; nj++) {
            int col = n0 + wn * 64 + nj * 8 + (lane & 3) * 2;
            float b0 = bias[mat * DMODEL + col], b1 = bias[mat * DMODEL + col + 1];
            float v00 = acc[mi][nj][0] + b0, v01 = acc[mi][nj][1] + b1;
            float v10 = acc[mi][nj][2] + b0, v11 = acc[mi][nj][3] + b1;
            if (F32OUT) {
                *(float2*)(Cf + (size_t)row * DMODEL + col)       = make_float2(v00, v01);
                *(float2*)(Cf + (size_t)(row + 8) * DMODEL + col) = make_float2(v10, v11);
            } else {
                size_t base = (size_t)mat * (MROWS * DMODEL);
                uint32_t hh, ll;
                split2(v00, v01, hh, ll);
                *(uint32_t*)(Chi + base + (size_t)row * DMODEL + col) = hh;
                *(uint32_t*)(Clo + base + (size_t)row * DMODEL + col) = ll;
                split2(v10, v11, hh, ll);
                *(uint32_t*)(Chi + base + (size_t)(row + 8) * DMODEL + col) = hh;
                *(uint32_t*)(Clo + base + (size_t)(row + 8) * DMODEL + col) = ll;
            }
        }
    }
}

// ================= HMMA flash attention (128-row Q tile, cp.async) ==========
// Block: (b, head, 128 q-rows). 256 threads (8 warps), warp owns 16 rows.
// K/V tiles 64 rows, double-buffered via cp.async.
// smem: Qh 0, Ql 18432 | stage s at 36864+s*36864: Kh 0, Kl 9216, Vh 18432, Vl 27648
//       pb at 110592 + s*256
#define FL_STAGE 36864
#define FL_SMEM  (110592 + 512)

__global__ __launch_bounds__(256)
void flash_mma_kernel(const __nv_bfloat16* __restrict__ Qh, const __nv_bfloat16* __restrict__ Ql,
                      const __nv_bfloat16* __restrict__ Kh, const __nv_bfloat16* __restrict__ Kl,
                      const __nv_bfloat16* __restrict__ Vh, const __nv_bfloat16* __restrict__ Vl,
                      const float* __restrict__ pb,
                      __nv_bfloat16* __restrict__ Ch, __nv_bfloat16* __restrict__ Cl) {
    extern __shared__ __align__(16) char sm[];
    const uint32_t sb = smem_u32(sm);
    const int tid = threadIdx.x, lane = tid & 31, wid = tid >> 5;
    const int qt = blockIdx.x, hh = blockIdx.y, b = blockIdx.z;
    const int rq0 = b * NTOK + qt * 128;

    // Q tile load: 128 rows x 8 segs, hi+lo
#pragma unroll
    for (int t = 0; t < 4; t++) {
        int u = tid + t * 256;
        int r = u >> 3, s = u & 7;
        size_t ga = (size_t)(rq0 + r) * DMODEL + hh * HD + s * 8;
        uint32_t d = (uint32_t)(r * GPB + s * 16);
        cp16(sb + d,          Qh + ga);
        cp16(sb + 18432 + d,  Ql + ga);
    }

    auto load_kv = [&](int stage, int kt) {
        uint32_t st = sb + 36864 + stage * FL_STAGE;
        int rk0 = b * NTOK + kt * 64;
#pragma unroll
        for (int t = 0; t < 2; t++) {
            int u = tid + t * 256;
            int r = u >> 3, s = u & 7;
            size_t ga = (size_t)(rk0 + r) * DMODEL + hh * HD + s * 8;
            uint32_t d = (uint32_t)(r * GPB + s * 16);
            cp16(st + d,         Kh + ga);
            cp16(st + 9216 + d,  Kl + ga);
            cp16(st + 18432 + d, Vh + ga);
            cp16(st + 27648 + d, Vl + ga);
        }
        if (tid < 16)
            cp16(sb + 110592 + stage * 256 + tid * 16, pb + rk0 + tid * 4);
    };

    load_kv(0, 0);
    CP_COMMIT();

    const int lr = (lane & 7) + ((lane >> 3) & 1) * 8;
    const int lk = (lane >> 4) * 8;

    uint32_t qfh[4][4], qfl[4][4];
    float o[8][4];
#pragma unroll
    for (int j = 0; j < 8; j++)
#pragma unroll
        for (int q = 0; q < 4; q++) o[j][q] = 0.0f;
    float mst0 = -1e30f, mst1 = -1e30f, lst0 = 0.0f, lst1 = 0.0f;

    for (int kt = 0; kt < NTOK / 64; kt++) {
        const int cur = kt & 1;
        CP_WAIT0();
        __syncthreads();
        if (kt == 0) {
#pragma unroll
            for (int ks = 0; ks < 4; ks++) {
                uint32_t off = (uint32_t)(wid * 16 + lr) * GPB + (ks * 16 + lk) * 2;
                ldsm_x4(qfh[ks], sb + off);
                ldsm_x4(qfl[ks], sb + 18432u + off);
            }
        }
        if (kt + 1 < NTOK / 64) {
            load_kv(cur ^ 1, kt + 1);
            CP_COMMIT();
        }
        const uint32_t st = sb + 36864 + cur * FL_STAGE;

        // S = Q K^T (3-pass split)
        float s[8][4];
#pragma unroll
        for (int j = 0; j < 8; j++)
#pragma unroll
            for (int q = 0; q < 4; q++) s[j][q] = 0.0f;

#pragma unroll
        for (int ks = 0; ks < 4; ks++) {
#pragma unroll
            for (int np = 0; np < 4; np++) {
                uint32_t off = (uint32_t)(np * 16 + lr) * GPB + (ks * 16 + lk) * 2;
                uint32_t bh[4], bl[4];
                ldsm_x4(bh, st + off);
                ldsm_x4(bl, st + 9216u + off);
                mma_bf16(s[2 * np],     qfh[ks], bh[0], bh[2]);
                mma_bf16(s[2 * np + 1], qfh[ks], bh[1], bh[3]);
                mma_bf16(s[2 * np],     qfh[ks], bl[0], bl[2]);
                mma_bf16(s[2 * np + 1], qfh[ks], bl[1], bl[3]);
                mma_bf16(s[2 * np],     qfl[ks], bh[0], bh[2]);
                mma_bf16(s[2 * np + 1], qfl[ks], bh[1], bh[3]);
            }
        }

        // softmax
        float mx0 = -1e30f, mx1 = -1e30f;
        const float* pbs = (const float*)(sm + 110592 + cur * 256);
#pragma unroll
        for (int j = 0; j < 8; j++) {
            int c = j * 8 + (lane & 3) * 2;
            float p0 = pbs[c], p1 = pbs[c + 1];
            s[j][0] = fmaf(s[j][0], 0.125f, p0);
            s[j][1] = fmaf(s[j][1], 0.125f, p1);
            s[j][2] = fmaf(s[j][2], 0.125f, p0);
            s[j][3] = fmaf(s[j][3], 0.125f, p1);
            mx0 = fmaxf(mx0, fmaxf(s[j][0], s[j][1]));
            mx1 = fmaxf(mx1, fmaxf(s[j][2], s[j][3]));
        }
        mx0 = fmaxf(mx0, __shfl_xor_sync(0xffffffffu, mx0, 1));
        mx0 = fmaxf(mx0, __shfl_xor_sync(0xffffffffu, mx0, 2));
        mx1 = fmaxf(mx1, __shfl_xor_sync(0xffffffffu, mx1, 1));
        mx1 = fmaxf(mx1, __shfl_xor_sync(0xffffffffu, mx1, 2));

        float mn0 = fmaxf(mst0, mx0), mn1 = fmaxf(mst1, mx1);
        float corr0 = __expf(mst0 - mn0), corr1 = __expf(mst1 - mn1);
        mst0 = mn0; mst1 = mn1;

        float sum0 = 0.0f, sum1 = 0.0f;
        uint32_t aph[4][4], apl[4][4];
#pragma unroll
        for (int j = 0; j < 8; j++) {
            float p0 = __expf(s[j][0] - mn0), p1 = __expf(s[j][1] - mn0);
            float p2 = __expf(s[j][2] - mn1), p3 = __expf(s[j][3] - mn1);
            sum0 += p0 + p1; sum1 += p2 + p3;
            uint32_t h01, l01, h23, l23;
            split2(p0, p1, h01, l01);
            split2(p2, p3, h23, l23);
            int ks = j >> 1, rb = (j & 1) * 2;
            aph[ks][rb] = h01; aph[ks][rb + 1] = h23;
            apl[ks][rb] = l01; apl[ks][rb + 1] = l23;
        }
        sum0 += __shfl_xor_sync(0xffffffffu, sum0, 1);
        sum0 += __shfl_xor_sync(0xffffffffu, sum0, 2);
        sum1 += __shfl_xor_sync(0xffffffffu, sum1, 1);
        sum1 += __shfl_xor_sync(0xffffffffu, sum1, 2);
        lst0 = lst0 * corr0 + sum0;
        lst1 = lst1 * corr1 + sum1;
#pragma unroll
        for (int j = 0; j < 8; j++) {
            o[j][0] *= corr0; o[j][1] *= corr0;
            o[j][2] *= corr1; o[j][3] *= corr1;
        }

        // O += P V (3-pass split)
#pragma unroll
        for (int ks = 0; ks < 4; ks++) {
#pragma unroll
            for (int np = 0; np < 4; np++) {
                uint32_t off = (uint32_t)(ks * 16 + lr) * GPB + (np * 16 + lk) * 2;
                uint32_t vh[4], vl[4];
                ldsm_x4t(vh, st + 18432u + off);
                ldsm_x4t(vl, st + 27648u + off);
                mma_bf16(o[2 * np],     aph[ks], vh[0], vh[1]);
                mma_bf16(o[2 * np + 1], aph[ks], vh[2], vh[3]);
                mma_bf16(o[2 * np],     aph[ks], vl[0], vl[1]);
                mma_bf16(o[2 * np + 1], aph[ks], vl[2], vl[3]);
                mma_bf16(o[2 * np],     apl[ks], vh[0], vh[1]);
                mma_bf16(o[2 * np + 1], apl[ks], vh[2], vh[3]);
            }
        }
        __syncthreads();
    }

    // epilogue
    float inv0 = 1.0f / lst0, inv1 = 1.0f / lst1;
    int row = rq0 + wid * 16 + (lane >> 2);
#pragma unroll
    for (int j = 0; j < 8; j++) {
        int col = hh * HD + j * 8 + (lane & 3) * 2;
        uint32_t hv, lv;
        split2(o[j][0] * inv0, o[j][1] * inv0, hv, lv);
        *(uint32_t*)(Ch + (size_t)row * DMODEL + col) = hv;
        *(uint32_t*)(Cl + (size_t)row * DMODEL + col) = lv;
        split2(o[j][2] * inv1, o[j][3] * inv1, hv, lv);
        *(uint32_t*)(Ch + (size_t)(row + 8) * DMODEL + col) = hv;
        *(uint32_t*)(Cl + (size_t)(row + 8) * DMODEL + col) = lv;
    }
}

// ---------------- launch ----------------------------------------------------
extern "C" void kernel_launch(void* const* d_in, const int* in_sizes, int n_in,
                              void* d_out, int out_size) {
    const float* h     = (const float*)d_in[0];
    const float* probs = (const float*)d_in[1];
    const float* Wq    = (const float*)d_in[2];
    const float* bq    = (const float*)d_in[3];
    const float* Wk    = (const float*)d_in[4];
    const float* bk    = (const float*)d_in[5];
    const float* Wv    = (const float*)d_in[6];
    const float* bv    = (const float*)d_in[7];
    const float* Wo    = (const float*)d_in[8];
    const float* bo    = (const float*)d_in[9];
    const float* pscal = (const float*)d_in[10];
    float* out = (float*)d_out;

    __nv_bfloat16 *hpeh, *hpel, *wh, *wl, *qkvh, *qkvl, *ctxh, *ctxl;
    float *pb, *b3;
    cudaGetSymbolAddress((void**)&hpeh, g_hpe_hi);
    cudaGetSymbolAddress((void**)&hpel, g_hpe_lo);
    cudaGetSymbolAddress((void**)&wh,   g_w_hi);
    cudaGetSymbolAddress((void**)&wl,   g_w_lo);
    cudaGetSymbolAddress((void**)&qkvh, g_qkv_hi);
    cudaGetSymbolAddress((void**)&qkvl, g_qkv_lo);
    cudaGetSymbolAddress((void**)&ctxh, g_ctx_hi);
    cudaGetSymbolAddress((void**)&ctxl, g_ctx_lo);
    cudaGetSymbolAddress((void**)&pb,   g_pb);
    cudaGetSymbolAddress((void**)&b3,   g_bias3);

    cudaFuncSetAttribute(gemm_cp_kernel<false>,
                         cudaFuncAttributeMaxDynamicSharedMemorySize, GEMM_SMEM);
    cudaFuncSetAttribute(gemm_cp_kernel<true>,
                         cudaFuncAttributeMaxDynamicSharedMemorySize, GEMM_SMEM);
    cudaFuncSetAttribute(flash_mma_kernel,
                         cudaFuncAttributeMaxDynamicSharedMemorySize, FL_SMEM);

    // prep
    build_hpe_split_kernel<<<MROWS * DMODEL / 4 / 256, 256>>>(h, hpeh, hpel);
    split_weights_kernel<<<dim3(DMODEL * DMODEL / 4 / 256, 4), 256>>>(Wq, Wk, Wv, Wo, wh, wl);
    build_pbias_kernel<<<(BATCH * NTOK + 255) / 256, 256>>>(probs, pscal, pb);
    pack_bias_kernel<<<(3 * DMODEL + 255) / 256, 256>>>(bq, bk, bv, b3);

    // fused QKV projection
    const size_t QKV = (size_t)MROWS * DMODEL;
    dim3 qkvgrid(3 * DMODEL / 128, MROWS / 128);    // (24, 32)
    gemm_cp_kernel<false><<<qkvgrid, 256, GEMM_SMEM>>>(hpeh, hpel, wh, wl, b3,
                                                       nullptr, qkvh, qkvl);

    // flash attention
    dim3 fgrid(NTOK / 128, HEADS, BATCH);           // (16, 16, 2)
    flash_mma_kernel<<<fgrid, 256, FL_SMEM>>>(qkvh, qkvl,
                                              qkvh + QKV, qkvl + QKV,
                                              qkvh + 2 * QKV, qkvl + 2 * QKV,
                                              pb, ctxh, ctxl);

    // output projection -> d_out (fp32)
    dim3 ogrid(DMODEL / 128, MROWS / 128);          // (8, 32)
    gemm_cp_kernel<true><<<ogrid, 256, GEMM_SMEM>>>(ctxh, ctxl, wh + 3 * WSZ, wl + 3 * WSZ, bo,
                                                    out, nullptr, nullptr);
}

// round 5
// speedup vs baseline: 1.0675x; 1.0675x over previous
#include <cuda_runtime.h>
#include <cuda_bf16.h>
#include <cstdint>
#include <cstddef>

#define BATCH   2
#define NTOK    2048
#define DMODEL  1024
#define HEADS   16
#define HD      64
#define MROWS   (BATCH*NTOK)  // 4096
#define WSZ     ((size_t)DMODEL * DMODEL)

// ======================= helpers ============================================
__device__ __forceinline__ uint32_t smem_u32(const void* p) {
    uint32_t a;
    asm("{ .reg .u64 t; cvta.to.shared.u64 t, %1; cvt.u32.u64 %0, t; }" : "=r"(a) : "l"(p));
    return a;
}
__device__ __forceinline__ void ldsm_x4(uint32_t r[4], uint32_t a) {
    asm volatile("ldmatrix.sync.aligned.m8n8.x4.shared.b16 {%0,%1,%2,%3}, [%4];"
        : "=r"(r[0]), "=r"(r[1]), "=r"(r[2]), "=r"(r[3]) : "r"(a));
}
__device__ __forceinline__ void ldsm_x4t(uint32_t r[4], uint32_t a) {
    asm volatile("ldmatrix.sync.aligned.m8n8.x4.trans.shared.b16 {%0,%1,%2,%3}, [%4];"
        : "=r"(r[0]), "=r"(r[1]), "=r"(r[2]), "=r"(r[3]) : "r"(a));
}
__device__ __forceinline__ void mma_bf16(float* c, const uint32_t* a, uint32_t b0, uint32_t b1) {
    asm volatile("mma.sync.aligned.m16n8k16.row.col.f32.bf16.bf16.f32 "
        "{%0,%1,%2,%3}, {%4,%5,%6,%7}, {%8,%9}, {%0,%1,%2,%3};"
        : "+f"(c[0]), "+f"(c[1]), "+f"(c[2]), "+f"(c[3])
        : "r"(a[0]), "r"(a[1]), "r"(a[2]), "r"(a[3]), "r"(b0), "r"(b1));
}
__device__ __forceinline__ void cp16(uint32_t sa, const void* g) {
    asm volatile("cp.async.cg.shared.global [%0], [%1], 16;"
        :: "r"(sa), "l"(__cvta_generic_to_global(g)) : "memory");
}
#define CP_COMMIT() asm volatile("cp.async.commit_group;" ::: "memory")
#define CP_WAIT0()  asm volatile("cp.async.wait_group 0;"  ::: "memory")

__device__ __forceinline__ ushort bfhi(float x) {
    return __bfloat16_as_ushort(__float2bfloat16(x));
}
__device__ __forceinline__ void split2(float a, float b, uint32_t& hi, uint32_t& lo) {
    ushort ah = bfhi(a), bh = bfhi(b);
    float ar = a - __bfloat162float(__ushort_as_bfloat16(ah));
    float br = b - __bfloat162float(__ushort_as_bfloat16(bh));
    hi = (uint32_t)ah | ((uint32_t)bh << 16);
    lo = (uint32_t)bfhi(ar) | ((uint32_t)bfhi(br) << 16);
}

// ======================= scratch (device globals) ===========================
__device__ __align__(16) __nv_bfloat16 g_hpe_hi[MROWS * DMODEL];
__device__ __align__(16) __nv_bfloat16 g_hpe_lo[MROWS * DMODEL];
__device__ __align__(16) __nv_bfloat16 g_w_hi[4 * DMODEL * DMODEL];
__device__ __align__(16) __nv_bfloat16 g_w_lo[4 * DMODEL * DMODEL];
__device__ __align__(16) __nv_bfloat16 g_qkv_hi[3 * MROWS * DMODEL];
__device__ __align__(16) __nv_bfloat16 g_qkv_lo[3 * MROWS * DMODEL];
__device__ __align__(16) __nv_bfloat16 g_ctx_hi[MROWS * DMODEL];
__device__ __align__(16) __nv_bfloat16 g_ctx_lo[MROWS * DMODEL];
__device__ __align__(16) float g_pb[BATCH * NTOK];
__device__ __align__(16) float g_bias3[3 * DMODEL];

// ======================= prep kernels =======================================
__global__ void build_hpe_split_kernel(const float* __restrict__ h,
                                       __nv_bfloat16* __restrict__ hi,
                                       __nv_bfloat16* __restrict__ lo) {
    int idx = blockIdx.x * blockDim.x + threadIdx.x;
    int row = idx >> 8;
    int d   = (idx & 255) * 4;
    int n   = row & (NTOK - 1);
    const float c1 = -9.210340371976184f / 1024.0f;
    float fn = (float)n;
    float div0 = expf((float)d * c1);
    float div1 = expf((float)(d + 2) * c1);
    float s0, c0, s1, c1v;
    sincosf(fn * div0, &s0, &c0);
    sincosf(fn * div1, &s1, &c1v);
    float4 v = reinterpret_cast<const float4*>(h)[idx];
    float x0 = v.x + s0, x1 = v.y + c0, x2 = v.z + s1, x3 = v.w + c1v;
    uint32_t h01, l01, h23, l23;
    split2(x0, x1, h01, l01);
    split2(x2, x3, h23, l23);
    reinterpret_cast<uint2*>(hi)[idx] = make_uint2(h01, h23);
    reinterpret_cast<uint2*>(lo)[idx] = make_uint2(l01, l23);
}

__global__ void split_weights_kernel(const float* __restrict__ Wq, const float* __restrict__ Wk,
                                     const float* __restrict__ Wv, const float* __restrict__ Wo,
                                     __nv_bfloat16* __restrict__ hi, __nv_bfloat16* __restrict__ lo) {
    int m = blockIdx.y;
    const float* src = (m == 0) ? Wq : (m == 1) ? Wk : (m == 2) ? Wv : Wo;
    int idx = blockIdx.x * blockDim.x + threadIdx.x;
    float4 v = reinterpret_cast<const float4*>(src)[idx];
    uint32_t h01, l01, h23, l23;
    split2(v.x, v.y, h01, l01);
    split2(v.z, v.w, h23, l23);
    size_t base = (size_t)m * (DMODEL * DMODEL / 4);
    reinterpret_cast<uint2*>(hi)[base + idx] = make_uint2(h01, h23);
    reinterpret_cast<uint2*>(lo)[base + idx] = make_uint2(l01, l23);
}

__global__ void build_pbias_kernel(const float* __restrict__ probs,
                                   const float* __restrict__ scale,
                                   float* __restrict__ pb) {
    int i = blockIdx.x * blockDim.x + threadIdx.x;
    if (i < BATCH * NTOK)
        pb[i] = scale[0] * logf(probs[i] + 1e-8f);
}

__global__ void pack_bias_kernel(const float* __restrict__ bq, const float* __restrict__ bk,
                                 const float* __restrict__ bv, float* __restrict__ b3) {
    int i = blockIdx.x * blockDim.x + threadIdx.x;
    if (i < DMODEL)           b3[i] = bq[i];
    else if (i < 2 * DMODEL)  b3[i] = bk[i - DMODEL];
    else if (i < 3 * DMODEL)  b3[i] = bv[i - 2 * DMODEL];
}

// ================= HMMA split-bf16 GEMM (cp.async, 2 CTA/SM) ================
// C[4096, Ntot] = A @ W^T + bias. Tile 128x128, K-chunk 32, 256 thr (8 warps).
// smem pitch 80B (32 bf16 + 16B pad). Stage = 4 x 128 x 80 = 40960 B.
#define GP32 80
#define G_STAGE 40960
#define GEMM_SMEM (2 * G_STAGE)   // 81920 -> 2 CTAs/SM

template<bool F32OUT>
__global__ __launch_bounds__(256, 2)
void gemm_cp_kernel(const __nv_bfloat16* __restrict__ Ahi, const __nv_bfloat16* __restrict__ Alo,
                    const __nv_bfloat16* __restrict__ Bhi, const __nv_bfloat16* __restrict__ Blo,
                    const float* __restrict__ bias,
                    float* __restrict__ Cf,
                    __nv_bfloat16* __restrict__ Chi, __nv_bfloat16* __restrict__ Clo) {
    extern __shared__ __align__(16) char sm[];
    const uint32_t sb = smem_u32(sm);

    const int tid = threadIdx.x, lane = tid & 31, wid = tid >> 5;
    const int wm = wid & 3, wn = wid >> 2;
    const int m0 = blockIdx.y * 128;
    const int ng = blockIdx.x * 128;
    const int mat = ng >> 10;
    const int n0 = ng & 1023;

    const __nv_bfloat16* Bh = Bhi + (size_t)mat * WSZ;
    const __nv_bfloat16* Bl = Blo + (size_t)mat * WSZ;

    // stage offsets: Ah 0, Al 10240, Bh 20480, Bl 30720
    auto load_stage = [&](int stage, int kc) {
        uint32_t st = sb + stage * G_STAGE;
#pragma unroll
        for (int t = 0; t < 2; t++) {
            int u = tid + t * 256;
            int r = u >> 2, s = u & 3;            // 128 rows x 4 segs of 16B
            uint32_t d = (uint32_t)(r * GP32 + s * 16);
            size_t ga = (size_t)(m0 + r) * DMODEL + kc * 32 + s * 8;
            cp16(st + d,          Ahi + ga);
            cp16(st + 10240 + d,  Alo + ga);
            size_t gb = (size_t)(n0 + r) * DMODEL + kc * 32 + s * 8;
            cp16(st + 20480 + d,  Bh + gb);
            cp16(st + 30720 + d,  Bl + gb);
        }
    };

    float acc[2][8][4];
#pragma unroll
    for (int mi = 0; mi < 2; mi++)
#pragma unroll
        for (int nj = 0; nj < 8; nj++)
#pragma unroll
            for (int q = 0; q < 4; q++) acc[mi][nj][q] = 0.0f;

    const int lr = (lane & 7) + ((lane >> 3) & 1) * 8;
    const int lk = (lane >> 4) * 8;

    load_stage(0, 0);
    CP_COMMIT();

    for (int kc = 0; kc < 32; kc++) {
        const int cur = kc & 1;
        CP_WAIT0();
        __syncthreads();
        if (kc + 1 < 32) {
            load_stage(cur ^ 1, kc + 1);
            CP_COMMIT();
        }
        const uint32_t st = sb + cur * G_STAGE;
#pragma unroll
        for (int ks = 0; ks < 2; ks++) {
            uint32_t ah[2][4], al[2][4];
#pragma unroll
            for (int mi = 0; mi < 2; mi++) {
                uint32_t off = (uint32_t)(wm * 32 + mi * 16 + lr) * GP32 + (ks * 16 + lk) * 2;
                ldsm_x4(ah[mi], st + off);
                ldsm_x4(al[mi], st + 10240u + off);
            }
#pragma unroll
            for (int np = 0; np < 4; np++) {
                uint32_t off = (uint32_t)(wn * 64 + np * 16 + lr) * GP32 + (ks * 16 + lk) * 2;
                uint32_t bh[4], bl[4];
                ldsm_x4(bh, st + 20480u + off);
                ldsm_x4(bl, st + 30720u + off);
#pragma unroll
                for (int mi = 0; mi < 2; mi++) {
                    mma_bf16(acc[mi][2 * np],     ah[mi], bh[0], bh[2]);
                    mma_bf16(acc[mi][2 * np + 1], ah[mi], bh[1], bh[3]);
                    mma_bf16(acc[mi][2 * np],     ah[mi], bl[0], bl[2]);
                    mma_bf16(acc[mi][2 * np + 1], ah[mi], bl[1], bl[3]);
                    mma_bf16(acc[mi][2 * np],     al[mi], bh[0], bh[2]);
                    mma_bf16(acc[mi][2 * np + 1], al[mi], bh[1], bh[3]);
                }
            }
        }
    }

    // epilogue
#pragma unroll
    for (int mi = 0; mi < 2; mi++) {
        int row = m0 + wm * 32 + mi * 16 + (lane >> 2);
#pragma unroll
        for (int nj = 0; nj < 8; nj++) {
            int col = n0 + wn * 64 + nj * 8 + (lane & 3) * 2;
            float b0 = bias[mat * DMODEL + col], b1 = bias[mat * DMODEL + col + 1];
            float v00 = acc[mi][nj][0] + b0, v01 = acc[mi][nj][1] + b1;
            float v10 = acc[mi][nj][2] + b0, v11 = acc[mi][nj][3] + b1;
            if (F32OUT) {
                *(float2*)(Cf + (size_t)row * DMODEL + col)       = make_float2(v00, v01);
                *(float2*)(Cf + (size_t)(row + 8) * DMODEL + col) = make_float2(v10, v11);
            } else {
                size_t base = (size_t)mat * (MROWS * DMODEL);
                uint32_t hh, ll;
                split2(v00, v01, hh, ll);
                *(uint32_t*)(Chi + base + (size_t)row * DMODEL + col) = hh;
                *(uint32_t*)(Clo + base + (size_t)row * DMODEL + col) = ll;
                split2(v10, v11, hh, ll);
                *(uint32_t*)(Chi + base + (size_t)(row + 8) * DMODEL + col) = hh;
                *(uint32_t*)(Clo + base + (size_t)(row + 8) * DMODEL + col) = ll;
            }
        }
    }
}

// ================= HMMA flash attention (Q in smem, 2 CTA/SM) ===============
// Block: (b, head, 128 q-rows). 256 threads (8 warps), warp owns 16 rows.
// Q persistent in smem (re-ldsm per K-tile to keep regs <= 128).
// smem: Qh 0, Ql 18432 | stage s at 36864+s*36864: Kh 0, Kl 9216, Vh 18432, Vl 27648
//       pb at 110592 + s*256
#define GPB 144
#define FL_STAGE 36864
#define FL_SMEM  (110592 + 512)   // 111104 -> 2 CTAs/SM

__global__ __launch_bounds__(256, 2)
void flash_mma_kernel(const __nv_bfloat16* __restrict__ Qh, const __nv_bfloat16* __restrict__ Ql,
                      const __nv_bfloat16* __restrict__ Kh, const __nv_bfloat16* __restrict__ Kl,
                      const __nv_bfloat16* __restrict__ Vh, const __nv_bfloat16* __restrict__ Vl,
                      const float* __restrict__ pb,
                      __nv_bfloat16* __restrict__ Ch, __nv_bfloat16* __restrict__ Cl) {
    extern __shared__ __align__(16) char sm[];
    const uint32_t sb = smem_u32(sm);
    const int tid = threadIdx.x, lane = tid & 31, wid = tid >> 5;
    const int qt = blockIdx.x, hh = blockIdx.y, b = blockIdx.z;
    const int rq0 = b * NTOK + qt * 128;

    // Q tile: 128 rows x 8 segs (16B), hi+lo
#pragma unroll
    for (int t = 0; t < 4; t++) {
        int u = tid + t * 256;
        int r = u >> 3, s = u & 7;
        size_t ga = (size_t)(rq0 + r) * DMODEL + hh * HD + s * 8;
        uint32_t d = (uint32_t)(r * GPB + s * 16);
        cp16(sb + d,          Qh + ga);
        cp16(sb + 18432 + d,  Ql + ga);
    }

    auto load_kv = [&](int stage, int kt) {
        uint32_t st = sb + 36864 + stage * FL_STAGE;
        int rk0 = b * NTOK + kt * 64;
#pragma unroll
        for (int t = 0; t < 2; t++) {
            int u = tid + t * 256;
            int r = u >> 3, s = u & 7;
            size_t ga = (size_t)(rk0 + r) * DMODEL + hh * HD + s * 8;
            uint32_t d = (uint32_t)(r * GPB + s * 16);
            cp16(st + d,         Kh + ga);
            cp16(st + 9216 + d,  Kl + ga);
            cp16(st + 18432 + d, Vh + ga);
            cp16(st + 27648 + d, Vl + ga);
        }
        if (tid < 16)
            cp16(sb + 110592 + stage * 256 + tid * 16, pb + rk0 + tid * 4);
    };

    load_kv(0, 0);
    CP_COMMIT();

    const int lr = (lane & 7) + ((lane >> 3) & 1) * 8;
    const int lk = (lane >> 4) * 8;

    float o[8][4];
#pragma unroll
    for (int j = 0; j < 8; j++)
#pragma unroll
        for (int q = 0; q < 4; q++) o[j][q] = 0.0f;
    float mst0 = -1e30f, mst1 = -1e30f, lst0 = 0.0f, lst1 = 0.0f;

    for (int kt = 0; kt < NTOK / 64; kt++) {
        const int cur = kt & 1;
        CP_WAIT0();
        __syncthreads();
        if (kt + 1 < NTOK / 64) {
            load_kv(cur ^ 1, kt + 1);
            CP_COMMIT();
        }
        const uint32_t st = sb + 36864 + cur * FL_STAGE;

        // S = Q K^T (3-pass split); Q frags re-loaded from smem per ks
        float s[8][4];
#pragma unroll
        for (int j = 0; j < 8; j++)
#pragma unroll
            for (int q = 0; q < 4; q++) s[j][q] = 0.0f;

#pragma unroll
        for (int ks = 0; ks < 4; ks++) {
            uint32_t qfh[4], qfl[4];
            uint32_t qoff = (uint32_t)(wid * 16 + lr) * GPB + (ks * 16 + lk) * 2;
            ldsm_x4(qfh, sb + qoff);
            ldsm_x4(qfl, sb + 18432u + qoff);
#pragma unroll
            for (int np = 0; np < 4; np++) {
                uint32_t off = (uint32_t)(np * 16 + lr) * GPB + (ks * 16 + lk) * 2;
                uint32_t bh[4], bl[4];
                ldsm_x4(bh, st + off);
                ldsm_x4(bl, st + 9216u + off);
                mma_bf16(s[2 * np],     qfh, bh[0], bh[2]);
                mma_bf16(s[2 * np + 1], qfh, bh[1], bh[3]);
                mma_bf16(s[2 * np],     qfh, bl[0], bl[2]);
                mma_bf16(s[2 * np + 1], qfh, bl[1], bl[3]);
                mma_bf16(s[2 * np],     qfl, bh[0], bh[2]);
                mma_bf16(s[2 * np + 1], qfl, bh[1], bh[3]);
            }
        }

        // softmax
        float mx0 = -1e30f, mx1 = -1e30f;
        const float* pbs = (const float*)(sm + 110592 + cur * 256);
#pragma unroll
        for (int j = 0; j < 8; j++) {
            int c = j * 8 + (lane & 3) * 2;
            float p0 = pbs[c], p1 = pbs[c + 1];
            s[j][0] = fmaf(s[j][0], 0.125f, p0);
            s[j][1] = fmaf(s[j][1], 0.125f, p1);
            s[j][2] = fmaf(s[j][2], 0.125f, p0);
            s[j][3] = fmaf(s[j][3], 0.125f, p1);
            mx0 = fmaxf(mx0, fmaxf(s[j][0], s[j][1]));
            mx1 = fmaxf(mx1, fmaxf(s[j][2], s[j][3]));
        }
        mx0 = fmaxf(mx0, __shfl_xor_sync(0xffffffffu, mx0, 1));
        mx0 = fmaxf(mx0, __shfl_xor_sync(0xffffffffu, mx0, 2));
        mx1 = fmaxf(mx1, __shfl_xor_sync(0xffffffffu, mx1, 1));
        mx1 = fmaxf(mx1, __shfl_xor_sync(0xffffffffu, mx1, 2));

        float mn0 = fmaxf(mst0, mx0), mn1 = fmaxf(mst1, mx1);
        float corr0 = __expf(mst0 - mn0), corr1 = __expf(mst1 - mn1);
        mst0 = mn0; mst1 = mn1;

        float sum0 = 0.0f, sum1 = 0.0f;
        uint32_t aph[4][4], apl[4][4];
#pragma unroll
        for (int j = 0; j < 8; j++) {
            float p0 = __expf(s[j][0] - mn0), p1 = __expf(s[j][1] - mn0);
            float p2 = __expf(s[j][2] - mn1), p3 = __expf(s[j][3] - mn1);
            sum0 += p0 + p1; sum1 += p2 + p3;
            uint32_t h01, l01, h23, l23;
            split2(p0, p1, h01, l01);
            split2(p2, p3, h23, l23);
            int ks = j >> 1, rb = (j & 1) * 2;
            aph[ks][rb] = h01; aph[ks][rb + 1] = h23;
            apl[ks][rb] = l01; apl[ks][rb + 1] = l23;
        }
        sum0 += __shfl_xor_sync(0xffffffffu, sum0, 1);
        sum0 += __shfl_xor_sync(0xffffffffu, sum0, 2);
        sum1 += __shfl_xor_sync(0xffffffffu, sum1, 1);
        sum1 += __shfl_xor_sync(0xffffffffu, sum1, 2);
        lst0 = lst0 * corr0 + sum0;
        lst1 = lst1 * corr1 + sum1;
#pragma unroll
        for (int j = 0; j < 8; j++) {
            o[j][0] *= corr0; o[j][1] *= corr0;
            o[j][2] *= corr1; o[j][3] *= corr1;
        }

        // O += P V (3-pass split)
#pragma unroll
        for (int ks = 0; ks < 4; ks++) {
#pragma unroll
            for (int np = 0; np < 4; np++) {
                uint32_t off = (uint32_t)(ks * 16 + lr) * GPB + (np * 16 + lk) * 2;
                uint32_t vh[4], vl[4];
                ldsm_x4t(vh, st + 18432u + off);
                ldsm_x4t(vl, st + 27648u + off);
                mma_bf16(o[2 * np],     aph[ks], vh[0], vh[1]);
                mma_bf16(o[2 * np + 1], aph[ks], vh[2], vh[3]);
                mma_bf16(o[2 * np],     aph[ks], vl[0], vl[1]);
                mma_bf16(o[2 * np + 1], aph[ks], vl[2], vl[3]);
                mma_bf16(o[2 * np],     apl[ks], vh[0], vh[1]);
                mma_bf16(o[2 * np + 1], apl[ks], vh[2], vh[3]);
            }
        }
    }

    // epilogue
    float inv0 = 1.0f / lst0, inv1 = 1.0f / lst1;
    int row = rq0 + wid * 16 + (lane >> 2);
#pragma unroll
    for (int j = 0; j < 8; j++) {
        int col = hh * HD + j * 8 + (lane & 3) * 2;
        uint32_t hv, lv;
        split2(o[j][0] * inv0, o[j][1] * inv0, hv, lv);
        *(uint32_t*)(Ch + (size_t)row * DMODEL + col) = hv;
        *(uint32_t*)(Cl + (size_t)row * DMODEL + col) = lv;
        split2(o[j][2] * inv1, o[j][3] * inv1, hv, lv);
        *(uint32_t*)(Ch + (size_t)(row + 8) * DMODEL + col) = hv;
        *(uint32_t*)(Cl + (size_t)(row + 8) * DMODEL + col) = lv;
    }
}

// ---------------- launch ----------------------------------------------------
extern "C" void kernel_launch(void* const* d_in, const int* in_sizes, int n_in,
                              void* d_out, int out_size) {
    const float* h     = (const float*)d_in[0];
    const float* probs = (const float*)d_in[1];
    const float* Wq    = (const float*)d_in[2];
    const float* bq    = (const float*)d_in[3];
    const float* Wk    = (const float*)d_in[4];
    const float* bk    = (const float*)d_in[5];
    const float* Wv    = (const float*)d_in[6];
    const float* bv    = (const float*)d_in[7];
    const float* Wo    = (const float*)d_in[8];
    const float* bo    = (const float*)d_in[9];
    const float* pscal = (const float*)d_in[10];
    float* out = (float*)d_out;

    __nv_bfloat16 *hpeh, *hpel, *wh, *wl, *qkvh, *qkvl, *ctxh, *ctxl;
    float *pb, *b3;
    cudaGetSymbolAddress((void**)&hpeh, g_hpe_hi);
    cudaGetSymbolAddress((void**)&hpel, g_hpe_lo);
    cudaGetSymbolAddress((void**)&wh,   g_w_hi);
    cudaGetSymbolAddress((void**)&wl,   g_w_lo);
    cudaGetSymbolAddress((void**)&qkvh, g_qkv_hi);
    cudaGetSymbolAddress((void**)&qkvl, g_qkv_lo);
    cudaGetSymbolAddress((void**)&ctxh, g_ctx_hi);
    cudaGetSymbolAddress((void**)&ctxl, g_ctx_lo);
    cudaGetSymbolAddress((void**)&pb,   g_pb);
    cudaGetSymbolAddress((void**)&b3,   g_bias3);

    cudaFuncSetAttribute(gemm_cp_kernel<false>,
                         cudaFuncAttributeMaxDynamicSharedMemorySize, GEMM_SMEM);
    cudaFuncSetAttribute(gemm_cp_kernel<true>,
                         cudaFuncAttributeMaxDynamicSharedMemorySize, GEMM_SMEM);
    cudaFuncSetAttribute(flash_mma_kernel,
                         cudaFuncAttributeMaxDynamicSharedMemorySize, FL_SMEM);

    // prep
    build_hpe_split_kernel<<<MROWS * DMODEL / 4 / 256, 256>>>(h, hpeh, hpel);
    split_weights_kernel<<<dim3(DMODEL * DMODEL / 4 / 256, 4), 256>>>(Wq, Wk, Wv, Wo, wh, wl);
    build_pbias_kernel<<<(BATCH * NTOK + 255) / 256, 256>>>(probs, pscal, pb);
    pack_bias_kernel<<<(3 * DMODEL + 255) / 256, 256>>>(bq, bk, bv, b3);

    // fused QKV projection
    const size_t QKV = (size_t)MROWS * DMODEL;
    dim3 qkvgrid(3 * DMODEL / 128, MROWS / 128);    // (24, 32)
    gemm_cp_kernel<false><<<qkvgrid, 256, GEMM_SMEM>>>(hpeh, hpel, wh, wl, b3,
                                                       nullptr, qkvh, qkvl);

    // flash attention
    dim3 fgrid(NTOK / 128, HEADS, BATCH);           // (16, 16, 2)
    flash_mma_kernel<<<fgrid, 256, FL_SMEM>>>(qkvh, qkvl,
                                              qkvh + QKV, qkvl + QKV,
                                              qkvh + 2 * QKV, qkvl + 2 * QKV,
                                              pb, ctxh, ctxl);

    // output projection -> d_out (fp32)
    dim3 ogrid(DMODEL / 128, MROWS / 128);          // (8, 32) — single wave at 2 CTA/SM
    gemm_cp_kernel<true><<<ogrid, 256, GEMM_SMEM>>>(ctxh, ctxl, wh + 3 * WSZ, wl + 3 * WSZ, bo,
                                                    out, nullptr, nullptr);
}